// round 10
// baseline (speedup 1.0000x reference)
#include <cuda_runtime.h>
#include <cuda_bf16.h>
#include <cstdint>

#define Bn 8
#define Ln 16384
#define Cn 128
#define Hn 4
#define Dn 32

// ---- scratch (device globals; no allocation allowed) ----
__device__ float g_kv[(size_t)Bn*256*Ln];            // [b, ch, l]: ch 0..127 = exp(k), 128..255 = v
__device__ __nv_bfloat16 g_qbh[(size_t)Bn*Ln*Cn];    // softmaxed q, hi bf16, [b, l, c]
__device__ __nv_bfloat16 g_qbl[(size_t)Bn*Ln*Cn];    // softmaxed q, lo bf16
__device__ float g_o[(size_t)Bn*Cn*Ln];              // pre-norm output [b, c, l]
__device__ float g_ctx[Bn*Hn*Dn*Dn];
__device__ float g_Z[Bn*Hn*Dn];
__device__ __nv_bfloat16 g_Ah[Bn*Cn*Cn];             // folded W_out@blockdiag(ctx), hi
__device__ __nv_bfloat16 g_Al[Bn*Cn*Cn];             // lo
__device__ float g_bsum[Bn];
__device__ float g_bsq[Bn];

// ---- SMEM layout (bytes). Tiles are bf16 with row pitch 136 (68 words). ----
#define PW32 68
#define X_H 0                 // 256 rows * 272B = 69632
#define X_L 69632
#define W_H 139264            // 128 rows * 272B = 34816
#define W_L 174080
#define SM_TOT 208896

// hi/lo bf16 split of a float pair -> packed bf16x2 words
__device__ __forceinline__ void split2(float a, float b, uint32_t& hi, uint32_t& lo) {
    __nv_bfloat162 hp = __floats2bfloat162_rn(a, b);
    hi = *(uint32_t*)&hp;
    __nv_bfloat162 lp = __floats2bfloat162_rn(a - __bfloat162float(hp.x),
                                              b - __bfloat162float(hp.y));
    lo = *(uint32_t*)&lp;
}

__device__ __forceinline__ void mma_bf16(float* c, const uint32_t* a, const uint32_t* b) {
    asm volatile(
        "mma.sync.aligned.m16n8k16.row.col.f32.bf16.bf16.f32 "
        "{%0,%1,%2,%3}, {%4,%5,%6,%7}, {%8,%9}, {%0,%1,%2,%3};"
        : "+f"(c[0]), "+f"(c[1]), "+f"(c[2]), "+f"(c[3])
        : "r"(a[0]), "r"(a[1]), "r"(a[2]), "r"(a[3]), "r"(b[0]), "r"(b[1]));
}

// 3-pass hi/lo GEMM core: acc[mf][nf][4] += A(128xK=128) x B(K=128 x N slice)
// Warp tile 64x64: mf 0..3 (16 rows each), nf 0..7 (8 cols each).
__device__ __forceinline__ void gemm3(const char* smem, float (*acc)[8][4],
                                      int WM, int WN, int g, int t) {
    for (int cb = 0; cb < 3; cb++) {
        const uint32_t* A32 = (const uint32_t*)(smem + (cb == 2 ? W_L : W_H));
        const uint32_t* B32 = (const uint32_t*)(smem + (cb == 1 ? X_L : X_H));
#pragma unroll
        for (int ks = 0; ks < 8; ks++) {
            int ko = ks * 8 + t;
            uint32_t a[4][4], bb[8][2];
#pragma unroll
            for (int mf = 0; mf < 4; mf++) {
                int r = (WM + mf * 16 + g) * PW32 + ko;
                a[mf][0] = A32[r];
                a[mf][1] = A32[r + 8 * PW32];
                a[mf][2] = A32[r + 4];
                a[mf][3] = A32[r + 8 * PW32 + 4];
            }
#pragma unroll
            for (int nf = 0; nf < 8; nf++) {
                int r = (WN + nf * 8 + g) * PW32 + ko;
                bb[nf][0] = B32[r];
                bb[nf][1] = B32[r + 4];
            }
#pragma unroll
            for (int mf = 0; mf < 4; mf++)
#pragma unroll
                for (int nf = 0; nf < 8; nf++)
                    mma_bf16(acc[mf][nf], a[mf], bb[nf]);
        }
    }
}

// ---- K0: zero accumulators (graph replays!) ----
__global__ void k_zero() {
    int i = blockIdx.x * 256 + threadIdx.x;
    if (i < Bn*Hn*Dn*Dn) g_ctx[i] = 0.f;
    if (i < Bn*Hn*Dn)    g_Z[i]   = 0.f;
    if (i < Bn)          { g_bsum[i] = 0.f; g_bsq[i] = 0.f; }
}

// ======== K1: HMMA QKV GEMM + fused q-softmax + exp(k) ========
// CTA: 256 positions x 3 m-tiles of 128 out channels, K=128.
__global__ __launch_bounds__(256, 1) void k_qkv_mma(const float* __restrict__ x,
                                                    const float* __restrict__ Wqkv) {
    extern __shared__ __align__(16) char smem[];
    int tid = threadIdx.x, wid = tid >> 5, lid = tid & 31;
    int g = lid >> 2, t = lid & 3;
    int WM = (wid & 1) * 64, WN = (wid >> 1) * 64;
    int p0 = blockIdx.x * 256;
    int b = p0 >> 14, l0 = p0 & (Ln - 1);
    uint32_t* XH = (uint32_t*)(smem + X_H);
    uint32_t* XL = (uint32_t*)(smem + X_L);
    uint32_t* WHp = (uint32_t*)(smem + W_H);
    uint32_t* WLp = (uint32_t*)(smem + W_L);

    // ---- load + split X tile: 256 pos x 128 ch ----
    const float4* x4 = (const float4*)(x + (size_t)p0 * Cn);
#pragma unroll
    for (int it = 0; it < 32; it++) {
        int f = it * 256 + tid, row = f >> 5, u = f & 31;
        float4 v = x4[f];
        uint32_t h0, l0w, h1, l1w;
        split2(v.x, v.y, h0, l0w);
        split2(v.z, v.w, h1, l1w);
        int wb = row * PW32 + u * 2;
        XH[wb] = h0; XH[wb + 1] = h1;
        XL[wb] = l0w; XL[wb + 1] = l1w;
    }

    for (int mt = 0; mt < 3; mt++) {
        // ---- load + split W m-tile: 128 x 128 ----
        const float4* w4 = (const float4*)(Wqkv + (size_t)mt * Cn * Cn);
#pragma unroll
        for (int it = 0; it < 16; it++) {
            int f = it * 256 + tid, row = f >> 5, u = f & 31;
            float4 v = w4[f];
            uint32_t h0, l0w, h1, l1w;
            split2(v.x, v.y, h0, l0w);
            split2(v.z, v.w, h1, l1w);
            int wb = row * PW32 + u * 2;
            WHp[wb] = h0; WHp[wb + 1] = h1;
            WLp[wb] = l0w; WLp[wb + 1] = l1w;
        }
        __syncthreads();

        float acc[4][8][4];
#pragma unroll
        for (int mf = 0; mf < 4; mf++)
#pragma unroll
            for (int nf = 0; nf < 8; nf++)
#pragma unroll
                for (int q = 0; q < 4; q++) acc[mf][nf][q] = 0.f;

        gemm3(smem, acc, WM, WN, g, t);
        __syncthreads();

        if (mt == 0) {
            // q: stage transposed in W region (2 rounds of 128 positions), softmax
            float* qs = (float*)(smem + W_H);
            for (int r = 0; r < 2; r++) {
                if ((WN >> 7) == r) {
#pragma unroll
                    for (int mf = 0; mf < 4; mf++)
#pragma unroll
                        for (int nf = 0; nf < 8; nf++) {
                            int m = WM + mf * 16 + g;
                            int nl = WN + nf * 8 + 2 * t - r * 128;
                            qs[nl * 129 + m]           = acc[mf][nf][0];
                            qs[(nl + 1) * 129 + m]     = acc[mf][nf][1];
                            qs[nl * 129 + m + 8]       = acc[mf][nf][2];
                            qs[(nl + 1) * 129 + m + 8] = acc[mf][nf][3];
                        }
                }
                __syncthreads();
                int pos = tid >> 1, hb = (tid & 1) * 64;
                size_t gq = ((size_t)(b * Ln + l0 + r * 128 + pos)) * Cn + hb;
#pragma unroll
                for (int hh = 0; hh < 2; hh++) {
                    float vv[32]; float mx = -1e30f;
#pragma unroll
                    for (int d = 0; d < 32; d++) {
                        vv[d] = qs[pos * 129 + hb + hh * 32 + d];
                        mx = fmaxf(mx, vv[d]);
                    }
                    float s = 0.f;
#pragma unroll
                    for (int d = 0; d < 32; d++) { vv[d] = __expf(vv[d] - mx); s += vv[d]; }
                    float inv = 0.17677669529663689f / s;   // d^-0.5 / s
                    uint32_t ph[16], pl[16];
#pragma unroll
                    for (int d2 = 0; d2 < 16; d2++)
                        split2(vv[2 * d2] * inv, vv[2 * d2 + 1] * inv, ph[d2], pl[d2]);
                    uint4* dh = (uint4*)(g_qbh + gq + hh * 32);
                    uint4* dl = (uint4*)(g_qbl + gq + hh * 32);
#pragma unroll
                    for (int w = 0; w < 4; w++) {
                        dh[w] = make_uint4(ph[4*w], ph[4*w+1], ph[4*w+2], ph[4*w+3]);
                        dl[w] = make_uint4(pl[4*w], pl[4*w+1], pl[4*w+2], pl[4*w+3]);
                    }
                }
                __syncthreads();
            }
        } else {
            // k -> exp(k); v -> raw; channel-major [b, ch, l]
            float* gk = g_kv + ((size_t)(b * 256 + (mt - 1) * 128)) * Ln + l0;
#pragma unroll
            for (int mf = 0; mf < 4; mf++)
#pragma unroll
                for (int nf = 0; nf < 8; nf++) {
                    int m = WM + mf * 16 + g;
                    int n0 = WN + nf * 8 + 2 * t;
                    float c0 = acc[mf][nf][0], c1 = acc[mf][nf][1];
                    float c2 = acc[mf][nf][2], c3 = acc[mf][nf][3];
                    if (mt == 1) {
                        c0 = __expf(c0); c1 = __expf(c1);
                        c2 = __expf(c2); c3 = __expf(c3);
                    }
                    *(float2*)(gk + (size_t)m * Ln + n0)       = make_float2(c0, c1);
                    *(float2*)(gk + (size_t)(m + 8) * Ln + n0) = make_float2(c2, c3);
                }
            __syncthreads();
        }
    }
}

// ---- K3: context[bh,c,d] += sum_j ek[c,j] v[d,j]; Z[bh,c] += sum_j ek[c,j] ----
__global__ __launch_bounds__(256) void k_ctx() {
    __shared__ float ks[32][33];
    __shared__ float vs[32][33];
    int t = threadIdx.x;
    int bh = blockIdx.x;
    int b = bh >> 2, h = bh & 3;
    const float* kbase = g_kv + (size_t)(b * 256 + h * Dn) * Ln;
    const float* vbase = g_kv + (size_t)(b * 256 + 128 + h * Dn) * Ln;
    int j0base = blockIdx.y * 1024;
    int g = t >> 6;
    int w = t & 63;
    int c4 = (w >> 3) * 4;
    int d4 = (w & 7) * 4;
    float acc[4][4];
#pragma unroll
    for (int i = 0; i < 4; i++)
#pragma unroll
        for (int k = 0; k < 4; k++) acc[i][k] = 0.f;
    float zl = 0.f;

    for (int jb = 0; jb < 32; jb++) {
        int j0 = j0base + jb * 32;
#pragma unroll
        for (int it = 0; it < 4; it++) {
            int idx = it * 256 + t;
            int c = idx >> 5, j = idx & 31;
            ks[c][j] = kbase[(size_t)c * Ln + j0 + j];
            vs[c][j] = vbase[(size_t)c * Ln + j0 + j];
        }
        __syncthreads();
#pragma unroll
        for (int jj = 0; jj < 8; jj++) {
            int j = g * 8 + jj;
            float e[4], v[4];
#pragma unroll
            for (int i = 0; i < 4; i++) { e[i] = ks[c4 + i][j]; v[i] = vs[d4 + i][j]; }
#pragma unroll
            for (int i = 0; i < 4; i++)
#pragma unroll
                for (int k = 0; k < 4; k++) acc[i][k] += e[i] * v[k];
        }
        if (w < 32) {
#pragma unroll
            for (int jj = 0; jj < 8; jj++) zl += ks[w][g * 8 + jj];
        }
        __syncthreads();
    }
#pragma unroll
    for (int i = 0; i < 4; i++)
#pragma unroll
        for (int k = 0; k < 4; k++)
            atomicAdd(&g_ctx[bh * 1024 + (c4 + i) * 32 + d4 + k], acc[i][k]);
    if (w < 32) atomicAdd(&g_Z[bh * 32 + w], zl);
}

// ---- K4: A_b = Wout @ blockdiag(ctx/Z), bf16 hi/lo. One output per thread. ----
// grid (64, Bn): blockIdx.y = b, 256 outputs per block (2 o-rows x 128 cols).
__global__ __launch_bounds__(256) void k_A(const float* __restrict__ Wout) {
    __shared__ float rZ[128];
    int t = threadIdx.x;
    int b = blockIdx.y;
    if (t < 128) rZ[t] = 1.f / g_Z[b * 128 + t];
    __syncthreads();
    int idx = blockIdx.x * 256 + t;        // 0..16383
    int o = idx >> 7, jcol = idx & 127;
    int h = jcol >> 5, d = jcol & 31;
    const float* wrow = Wout + o * Cn + h * Dn;      // warp-uniform (broadcast)
    const float* cb = g_ctx + b * 4096 + h * 1024 + d;  // lanes d coalesce
    const float* rz = rZ + h * Dn;
    float s = 0.f;
#pragma unroll
    for (int c = 0; c < 32; c++) s += wrow[c] * rz[c] * cb[c * 32];
    __nv_bfloat16 hb = __float2bfloat16(s);
    g_Ah[b * Cn * Cn + idx] = hb;
    g_Al[b * Cn * Cn + idx] = __float2bfloat16(s - __bfloat162float(hb));
}

// ======== K5: HMMA out GEMM: o = A_b @ q + bias; accumulate sum/sumsq ========
__global__ __launch_bounds__(256, 1) void k_out_mma(const float* __restrict__ bout) {
    extern __shared__ __align__(16) char smem[];
    int tid = threadIdx.x, wid = tid >> 5, lid = tid & 31;
    int g = lid >> 2, t = lid & 3;
    int WM = (wid & 1) * 64, WN = (wid >> 1) * 64;
    int p0 = blockIdx.x * 256;
    int b = p0 >> 14, l0 = p0 & (Ln - 1);
    uint32_t* XH = (uint32_t*)(smem + X_H);
    uint32_t* XL = (uint32_t*)(smem + X_L);
    uint32_t* WHp = (uint32_t*)(smem + W_H);
    uint32_t* WLp = (uint32_t*)(smem + W_L);

    // Q tiles (already bf16 hi/lo, [l][c] K-major rows of 256B)
    const uint4* qh4 = (const uint4*)(g_qbh + (size_t)p0 * Cn);
    const uint4* ql4 = (const uint4*)(g_qbl + (size_t)p0 * Cn);
#pragma unroll
    for (int it = 0; it < 16; it++) {
        int f = it * 256 + tid, row = f >> 4, u = f & 15;
        *(uint4*)(XH + row * PW32 + u * 4) = qh4[f];
        *(uint4*)(XL + row * PW32 + u * 4) = ql4[f];
    }
    // A tiles
    const uint4* ah4 = (const uint4*)(g_Ah + (size_t)b * Cn * Cn);
    const uint4* al4 = (const uint4*)(g_Al + (size_t)b * Cn * Cn);
#pragma unroll
    for (int it = 0; it < 8; it++) {
        int f = it * 256 + tid, row = f >> 4, u = f & 15;
        *(uint4*)(WHp + row * PW32 + u * 4) = ah4[f];
        *(uint4*)(WLp + row * PW32 + u * 4) = al4[f];
    }
    __syncthreads();

    float acc[4][8][4];
#pragma unroll
    for (int mf = 0; mf < 4; mf++)
#pragma unroll
        for (int nf = 0; nf < 8; nf++)
#pragma unroll
            for (int q = 0; q < 4; q++) acc[mf][nf][q] = 0.f;

    gemm3(smem, acc, WM, WN, g, t);

    float lsum = 0.f, lsq = 0.f;
    float* go = g_o + ((size_t)b * Cn) * Ln + l0;
#pragma unroll
    for (int mf = 0; mf < 4; mf++) {
        int m = WM + mf * 16 + g;
        float b0v = bout[m], b1v = bout[m + 8];
#pragma unroll
        for (int nf = 0; nf < 8; nf++) {
            int n0 = WN + nf * 8 + 2 * t;
            float c0 = acc[mf][nf][0] + b0v, c1 = acc[mf][nf][1] + b0v;
            float c2 = acc[mf][nf][2] + b1v, c3 = acc[mf][nf][3] + b1v;
            lsum += c0 + c1 + c2 + c3;
            lsq  += c0 * c0 + c1 * c1 + c2 * c2 + c3 * c3;
            *(float2*)(go + (size_t)m * Ln + n0)       = make_float2(c0, c1);
            *(float2*)(go + (size_t)(m + 8) * Ln + n0) = make_float2(c2, c3);
        }
    }
    // warp shuffle reduce + one atomic per warp
#pragma unroll
    for (int off = 16; off > 0; off >>= 1) {
        lsum += __shfl_xor_sync(0xFFFFFFFFu, lsum, off);
        lsq  += __shfl_xor_sync(0xFFFFFFFFu, lsq, off);
    }
    if (lid == 0) {
        atomicAdd(&g_bsum[b], lsum);
        atomicAdd(&g_bsq[b], lsq);
    }
}

// ---- K6: GroupNorm(1,C) + transpose to [b, l, c] ----
__global__ void k_norm(const float* __restrict__ gnw, const float* __restrict__ gnb,
                       float* __restrict__ out) {
    __shared__ float tile[32][33];
    int b  = blockIdx.z;
    int c0 = blockIdx.y * 32;
    int l0 = blockIdx.x * 32;
    const float n = 2097152.0f;           // C*L
    float mean = g_bsum[b] / n;
    float var  = g_bsq[b] / n - mean * mean;
    float rstd = rsqrtf(var + 1e-5f);
    int tx = threadIdx.x, ty = threadIdx.y;
#pragma unroll
    for (int r = 0; r < 4; r++) {
        int cy = ty * 4 + r;
        tile[cy][tx] = g_o[(size_t)(b * Cn + c0 + cy) * Ln + l0 + tx];
    }
    __syncthreads();
#pragma unroll
    for (int r = 0; r < 4; r++) {
        int ly = ty * 4 + r;
        int cch = c0 + tx;
        float v = (tile[tx][ly] - mean) * rstd * gnw[cch] + gnb[cch];
        out[(size_t)(b * Ln + l0 + ly) * Cn + cch] = v;
    }
}

extern "C" void kernel_launch(void* const* d_in, const int* in_sizes, int n_in,
                              void* d_out, int out_size) {
    const float* x    = (const float*)d_in[0];
    const float* Wqkv = (const float*)d_in[1];
    const float* Wout = (const float*)d_in[2];
    const float* bout = (const float*)d_in[3];
    const float* gnw  = (const float*)d_in[4];
    const float* gnb  = (const float*)d_in[5];
    float* out = (float*)d_out;

    cudaFuncSetAttribute(k_qkv_mma, cudaFuncAttributeMaxDynamicSharedMemorySize, SM_TOT);
    cudaFuncSetAttribute(k_out_mma, cudaFuncAttributeMaxDynamicSharedMemorySize, SM_TOT);

    k_zero<<<128, 256>>>();
    k_qkv_mma<<<(Bn * Ln) / 256, 256, SM_TOT>>>(x, Wqkv);
    k_ctx<<<dim3(Bn * Hn, 16), 256>>>();
    k_A<<<dim3(64, Bn), 256>>>(Wout);
    k_out_mma<<<(Bn * Ln) / 256, 256, SM_TOT>>>(bout);
    k_norm<<<dim3(Ln / 32, Cn / 32, Bn), dim3(32, 8)>>>(gnw, gnb, out);
}

// round 11
// speedup vs baseline: 1.4399x; 1.4399x over previous
#include <cuda_runtime.h>
#include <cuda_bf16.h>
#include <cstdint>

#define Bn 8
#define Ln 16384
#define Cn 128
#define Hn 4
#define Dn 32

// ---- scratch (device globals; no allocation allowed) ----
__device__ float g_kv[(size_t)Bn*256*Ln];            // [b, ch, l]: ch 0..127 = exp(k), 128..255 = v
__device__ __nv_bfloat16 g_qbh[(size_t)Bn*Ln*Cn];    // softmaxed q, hi bf16, [b, l, c]
__device__ __nv_bfloat16 g_qbl[(size_t)Bn*Ln*Cn];    // softmaxed q, lo bf16
__device__ float g_o[(size_t)Bn*Cn*Ln];              // pre-norm output [b, c, l]
__device__ float g_ctx[Bn*Hn*Dn*Dn];
__device__ float g_Z[Bn*Hn*Dn];
__device__ __nv_bfloat16 g_Ah[Bn*Cn*Cn];             // folded W_out@blockdiag(ctx), hi
__device__ __nv_bfloat16 g_Al[Bn*Cn*Cn];             // lo
__device__ float g_bsum[Bn];
__device__ float g_bsq[Bn];

// ---- SMEM layout (bytes). Tiles are bf16 with row pitch 136 (68 words). ----
#define PW32 68
#define X_H 0                 // 256 rows * 272B = 69632
#define X_L 69632
#define W_H 139264            // 128 rows * 272B = 34816
#define W_L 174080
#define SM_TOT 208896

// hi/lo bf16 split of a float pair -> packed bf16x2 words
__device__ __forceinline__ void split2(float a, float b, uint32_t& hi, uint32_t& lo) {
    __nv_bfloat162 hp = __floats2bfloat162_rn(a, b);
    hi = *(uint32_t*)&hp;
    __nv_bfloat162 lp = __floats2bfloat162_rn(a - __bfloat162float(hp.x),
                                              b - __bfloat162float(hp.y));
    lo = *(uint32_t*)&lp;
}

__device__ __forceinline__ void mma_bf16(float* c, const uint32_t* a, const uint32_t* b) {
    asm volatile(
        "mma.sync.aligned.m16n8k16.row.col.f32.bf16.bf16.f32 "
        "{%0,%1,%2,%3}, {%4,%5,%6,%7}, {%8,%9}, {%0,%1,%2,%3};"
        : "+f"(c[0]), "+f"(c[1]), "+f"(c[2]), "+f"(c[3])
        : "r"(a[0]), "r"(a[1]), "r"(a[2]), "r"(a[3]), "r"(b[0]), "r"(b[1]));
}

// 3-pass hi/lo GEMM core: acc[mf][nf][4] += A(128xK=128) x B(K=128 x N slice)
// Warp tile 64x64: mf 0..3 (16 rows each), nf 0..7 (8 cols each).
__device__ __forceinline__ void gemm3(const char* smem, float (*acc)[8][4],
                                      int WM, int WN, int g, int t) {
    for (int cb = 0; cb < 3; cb++) {
        const uint32_t* A32 = (const uint32_t*)(smem + (cb == 2 ? W_L : W_H));
        const uint32_t* B32 = (const uint32_t*)(smem + (cb == 1 ? X_L : X_H));
#pragma unroll
        for (int ks = 0; ks < 8; ks++) {
            int ko = ks * 8 + t;
            uint32_t a[4][4], bb[8][2];
#pragma unroll
            for (int mf = 0; mf < 4; mf++) {
                int r = (WM + mf * 16 + g) * PW32 + ko;
                a[mf][0] = A32[r];
                a[mf][1] = A32[r + 8 * PW32];
                a[mf][2] = A32[r + 4];
                a[mf][3] = A32[r + 8 * PW32 + 4];
            }
#pragma unroll
            for (int nf = 0; nf < 8; nf++) {
                int r = (WN + nf * 8 + g) * PW32 + ko;
                bb[nf][0] = B32[r];
                bb[nf][1] = B32[r + 4];
            }
#pragma unroll
            for (int mf = 0; mf < 4; mf++)
#pragma unroll
                for (int nf = 0; nf < 8; nf++)
                    mma_bf16(acc[mf][nf], a[mf], bb[nf]);
        }
    }
}

// ---- K0: zero accumulators (graph replays!) ----
__global__ void k_zero() {
    int i = blockIdx.x * 256 + threadIdx.x;
    if (i < Bn*Hn*Dn*Dn) g_ctx[i] = 0.f;
    if (i < Bn*Hn*Dn)    g_Z[i]   = 0.f;
    if (i < Bn)          { g_bsum[i] = 0.f; g_bsq[i] = 0.f; }
}

// ======== K1: HMMA QKV GEMM + fused q-softmax + exp(k) ========
// CTA: 256 positions x 3 m-tiles of 128 out channels, K=128.
__global__ __launch_bounds__(256, 1) void k_qkv_mma(const float* __restrict__ x,
                                                    const float* __restrict__ Wqkv) {
    extern __shared__ __align__(16) char smem[];
    int tid = threadIdx.x, wid = tid >> 5, lid = tid & 31;
    int g = lid >> 2, t = lid & 3;
    int WM = (wid & 1) * 64, WN = (wid >> 1) * 64;
    int p0 = blockIdx.x * 256;
    int b = p0 >> 14, l0 = p0 & (Ln - 1);
    uint32_t* XH = (uint32_t*)(smem + X_H);
    uint32_t* XL = (uint32_t*)(smem + X_L);
    uint32_t* WHp = (uint32_t*)(smem + W_H);
    uint32_t* WLp = (uint32_t*)(smem + W_L);

    // ---- load + split X tile: 256 pos x 128 ch ----
    const float4* x4 = (const float4*)(x + (size_t)p0 * Cn);
#pragma unroll
    for (int it = 0; it < 32; it++) {
        int f = it * 256 + tid, row = f >> 5, u = f & 31;
        float4 v = x4[f];
        uint32_t h0, l0w, h1, l1w;
        split2(v.x, v.y, h0, l0w);
        split2(v.z, v.w, h1, l1w);
        int wb = row * PW32 + u * 2;
        XH[wb] = h0; XH[wb + 1] = h1;
        XL[wb] = l0w; XL[wb + 1] = l1w;
    }

    for (int mt = 0; mt < 3; mt++) {
        // ---- load + split W m-tile: 128 x 128 ----
        const float4* w4 = (const float4*)(Wqkv + (size_t)mt * Cn * Cn);
#pragma unroll
        for (int it = 0; it < 16; it++) {
            int f = it * 256 + tid, row = f >> 5, u = f & 31;
            float4 v = w4[f];
            uint32_t h0, l0w, h1, l1w;
            split2(v.x, v.y, h0, l0w);
            split2(v.z, v.w, h1, l1w);
            int wb = row * PW32 + u * 2;
            WHp[wb] = h0; WHp[wb + 1] = h1;
            WLp[wb] = l0w; WLp[wb + 1] = l1w;
        }
        __syncthreads();

        float acc[4][8][4];
#pragma unroll
        for (int mf = 0; mf < 4; mf++)
#pragma unroll
            for (int nf = 0; nf < 8; nf++)
#pragma unroll
                for (int q = 0; q < 4; q++) acc[mf][nf][q] = 0.f;

        gemm3(smem, acc, WM, WN, g, t);
        __syncthreads();

        if (mt == 0) {
            // q: stage transposed in W region (2 rounds of 128 positions), softmax
            float* qs = (float*)(smem + W_H);
            for (int r = 0; r < 2; r++) {
                if ((WN >> 7) == r) {
#pragma unroll
                    for (int mf = 0; mf < 4; mf++)
#pragma unroll
                        for (int nf = 0; nf < 8; nf++) {
                            int m = WM + mf * 16 + g;
                            int nl = WN + nf * 8 + 2 * t - r * 128;
                            qs[nl * 129 + m]           = acc[mf][nf][0];
                            qs[(nl + 1) * 129 + m]     = acc[mf][nf][1];
                            qs[nl * 129 + m + 8]       = acc[mf][nf][2];
                            qs[(nl + 1) * 129 + m + 8] = acc[mf][nf][3];
                        }
                }
                __syncthreads();
                int pos = tid >> 1, hb = (tid & 1) * 64;
                size_t gq = ((size_t)(b * Ln + l0 + r * 128 + pos)) * Cn + hb;
#pragma unroll
                for (int hh = 0; hh < 2; hh++) {
                    float vv[32]; float mx = -1e30f;
#pragma unroll
                    for (int d = 0; d < 32; d++) {
                        vv[d] = qs[pos * 129 + hb + hh * 32 + d];
                        mx = fmaxf(mx, vv[d]);
                    }
                    float s = 0.f;
#pragma unroll
                    for (int d = 0; d < 32; d++) { vv[d] = __expf(vv[d] - mx); s += vv[d]; }
                    float inv = 0.17677669529663689f / s;   // d^-0.5 / s
                    uint32_t ph[16], pl[16];
#pragma unroll
                    for (int d2 = 0; d2 < 16; d2++)
                        split2(vv[2 * d2] * inv, vv[2 * d2 + 1] * inv, ph[d2], pl[d2]);
                    uint4* dh = (uint4*)(g_qbh + gq + hh * 32);
                    uint4* dl = (uint4*)(g_qbl + gq + hh * 32);
#pragma unroll
                    for (int w = 0; w < 4; w++) {
                        dh[w] = make_uint4(ph[4*w], ph[4*w+1], ph[4*w+2], ph[4*w+3]);
                        dl[w] = make_uint4(pl[4*w], pl[4*w+1], pl[4*w+2], pl[4*w+3]);
                    }
                }
                __syncthreads();
            }
        } else {
            // k -> exp(k); v -> raw; channel-major [b, ch, l]
            float* gk = g_kv + ((size_t)(b * 256 + (mt - 1) * 128)) * Ln + l0;
#pragma unroll
            for (int mf = 0; mf < 4; mf++)
#pragma unroll
                for (int nf = 0; nf < 8; nf++) {
                    int m = WM + mf * 16 + g;
                    int n0 = WN + nf * 8 + 2 * t;
                    float c0 = acc[mf][nf][0], c1 = acc[mf][nf][1];
                    float c2 = acc[mf][nf][2], c3 = acc[mf][nf][3];
                    if (mt == 1) {
                        c0 = __expf(c0); c1 = __expf(c1);
                        c2 = __expf(c2); c3 = __expf(c3);
                    }
                    *(float2*)(gk + (size_t)m * Ln + n0)       = make_float2(c0, c1);
                    *(float2*)(gk + (size_t)(m + 8) * Ln + n0) = make_float2(c2, c3);
                }
            __syncthreads();
        }
    }
}

// ---- K3: context[bh,c,d] += sum_j ek[c,j] v[d,j]; Z[bh,c] += sum_j ek[c,j] ----
__global__ __launch_bounds__(256) void k_ctx() {
    __shared__ float ks[32][33];
    __shared__ float vs[32][33];
    int t = threadIdx.x;
    int bh = blockIdx.x;
    int b = bh >> 2, h = bh & 3;
    const float* kbase = g_kv + (size_t)(b * 256 + h * Dn) * Ln;
    const float* vbase = g_kv + (size_t)(b * 256 + 128 + h * Dn) * Ln;
    int j0base = blockIdx.y * 1024;
    int g = t >> 6;
    int w = t & 63;
    int c4 = (w >> 3) * 4;
    int d4 = (w & 7) * 4;
    float acc[4][4];
#pragma unroll
    for (int i = 0; i < 4; i++)
#pragma unroll
        for (int k = 0; k < 4; k++) acc[i][k] = 0.f;
    float zl = 0.f;

    for (int jb = 0; jb < 32; jb++) {
        int j0 = j0base + jb * 32;
#pragma unroll
        for (int it = 0; it < 4; it++) {
            int idx = it * 256 + t;
            int c = idx >> 5, j = idx & 31;
            ks[c][j] = kbase[(size_t)c * Ln + j0 + j];
            vs[c][j] = vbase[(size_t)c * Ln + j0 + j];
        }
        __syncthreads();
#pragma unroll
        for (int jj = 0; jj < 8; jj++) {
            int j = g * 8 + jj;
            float e[4], v[4];
#pragma unroll
            for (int i = 0; i < 4; i++) { e[i] = ks[c4 + i][j]; v[i] = vs[d4 + i][j]; }
#pragma unroll
            for (int i = 0; i < 4; i++)
#pragma unroll
                for (int k = 0; k < 4; k++) acc[i][k] += e[i] * v[k];
        }
        if (w < 32) {
#pragma unroll
            for (int jj = 0; jj < 8; jj++) zl += ks[w][g * 8 + jj];
        }
        __syncthreads();
    }
#pragma unroll
    for (int i = 0; i < 4; i++)
#pragma unroll
        for (int k = 0; k < 4; k++)
            atomicAdd(&g_ctx[bh * 1024 + (c4 + i) * 32 + d4 + k], acc[i][k]);
    if (w < 32) atomicAdd(&g_Z[bh * 32 + w], zl);
}

// ---- K4: A_b = Wout @ blockdiag(ctx/Z), bf16 hi/lo. One output per thread. ----
// grid (64, Bn): blockIdx.y = b, 256 outputs per block (2 o-rows x 128 cols).
__global__ __launch_bounds__(256) void k_A(const float* __restrict__ Wout) {
    __shared__ float rZ[128];
    int t = threadIdx.x;
    int b = blockIdx.y;
    if (t < 128) rZ[t] = 1.f / g_Z[b * 128 + t];
    __syncthreads();
    int idx = blockIdx.x * 256 + t;        // 0..16383
    int o = idx >> 7, jcol = idx & 127;
    int h = jcol >> 5, d = jcol & 31;
    const float* wrow = Wout + o * Cn + h * Dn;      // warp-uniform (broadcast)
    const float* cb = g_ctx + b * 4096 + h * 1024 + d;  // lanes d coalesce
    const float* rz = rZ + h * Dn;
    float s = 0.f;
#pragma unroll
    for (int c = 0; c < 32; c++) s += wrow[c] * rz[c] * cb[c * 32];
    __nv_bfloat16 hb = __float2bfloat16(s);
    g_Ah[b * Cn * Cn + idx] = hb;
    g_Al[b * Cn * Cn + idx] = __float2bfloat16(s - __bfloat162float(hb));
}

// ======== K5: HMMA out GEMM: o = A_b @ q + bias; accumulate sum/sumsq ========
__global__ __launch_bounds__(256, 1) void k_out_mma(const float* __restrict__ bout) {
    extern __shared__ __align__(16) char smem[];
    int tid = threadIdx.x, wid = tid >> 5, lid = tid & 31;
    int g = lid >> 2, t = lid & 3;
    int WM = (wid & 1) * 64, WN = (wid >> 1) * 64;
    int p0 = blockIdx.x * 256;
    int b = p0 >> 14, l0 = p0 & (Ln - 1);
    uint32_t* XH = (uint32_t*)(smem + X_H);
    uint32_t* XL = (uint32_t*)(smem + X_L);
    uint32_t* WHp = (uint32_t*)(smem + W_H);
    uint32_t* WLp = (uint32_t*)(smem + W_L);

    // Q tiles (already bf16 hi/lo, [l][c] K-major rows of 256B)
    const uint4* qh4 = (const uint4*)(g_qbh + (size_t)p0 * Cn);
    const uint4* ql4 = (const uint4*)(g_qbl + (size_t)p0 * Cn);
#pragma unroll
    for (int it = 0; it < 16; it++) {
        int f = it * 256 + tid, row = f >> 4, u = f & 15;
        *(uint4*)(XH + row * PW32 + u * 4) = qh4[f];
        *(uint4*)(XL + row * PW32 + u * 4) = ql4[f];
    }
    // A tiles
    const uint4* ah4 = (const uint4*)(g_Ah + (size_t)b * Cn * Cn);
    const uint4* al4 = (const uint4*)(g_Al + (size_t)b * Cn * Cn);
#pragma unroll
    for (int it = 0; it < 8; it++) {
        int f = it * 256 + tid, row = f >> 4, u = f & 15;
        *(uint4*)(WHp + row * PW32 + u * 4) = ah4[f];
        *(uint4*)(WLp + row * PW32 + u * 4) = al4[f];
    }
    __syncthreads();

    float acc[4][8][4];
#pragma unroll
    for (int mf = 0; mf < 4; mf++)
#pragma unroll
        for (int nf = 0; nf < 8; nf++)
#pragma unroll
            for (int q = 0; q < 4; q++) acc[mf][nf][q] = 0.f;

    gemm3(smem, acc, WM, WN, g, t);
    __syncthreads();

    float lsum = 0.f, lsq = 0.f;
    float* go = g_o + ((size_t)b * Cn) * Ln + l0;
#pragma unroll
    for (int mf = 0; mf < 4; mf++) {
        int m = WM + mf * 16 + g;
        float b0v = bout[m], b1v = bout[m + 8];
#pragma unroll
        for (int nf = 0; nf < 8; nf++) {
            int n0 = WN + nf * 8 + 2 * t;
            float c0 = acc[mf][nf][0] + b0v, c1 = acc[mf][nf][1] + b0v;
            float c2 = acc[mf][nf][2] + b1v, c3 = acc[mf][nf][3] + b1v;
            lsum += c0 + c1 + c2 + c3;
            lsq  += c0 * c0 + c1 * c1 + c2 * c2 + c3 * c3;
            *(float2*)(go + (size_t)m * Ln + n0)       = make_float2(c0, c1);
            *(float2*)(go + (size_t)(m + 8) * Ln + n0) = make_float2(c2, c3);
        }
    }
    float* red = (float*)(smem + W_H);
    red[tid] = lsum; __syncthreads();
    for (int s = 128; s > 0; s >>= 1) { if (tid < s) red[tid] += red[tid + s]; __syncthreads(); }
    if (tid == 0) atomicAdd(&g_bsum[b], red[0]);
    __syncthreads();
    red[tid] = lsq; __syncthreads();
    for (int s = 128; s > 0; s >>= 1) { if (tid < s) red[tid] += red[tid + s]; __syncthreads(); }
    if (tid == 0) atomicAdd(&g_bsq[b], red[0]);
}

// ---- K6: GroupNorm(1,C) + transpose to [b, l, c] ----
__global__ void k_norm(const float* __restrict__ gnw, const float* __restrict__ gnb,
                       float* __restrict__ out) {
    __shared__ float tile[32][33];
    int b  = blockIdx.z;
    int c0 = blockIdx.y * 32;
    int l0 = blockIdx.x * 32;
    const float n = 2097152.0f;           // C*L
    float mean = g_bsum[b] / n;
    float var  = g_bsq[b] / n - mean * mean;
    float rstd = rsqrtf(var + 1e-5f);
    int tx = threadIdx.x, ty = threadIdx.y;
#pragma unroll
    for (int r = 0; r < 4; r++) {
        int cy = ty * 4 + r;
        tile[cy][tx] = g_o[(size_t)(b * Cn + c0 + cy) * Ln + l0 + tx];
    }
    __syncthreads();
#pragma unroll
    for (int r = 0; r < 4; r++) {
        int ly = ty * 4 + r;
        int cch = c0 + tx;
        float v = (tile[tx][ly] - mean) * rstd * gnw[cch] + gnb[cch];
        out[(size_t)(b * Ln + l0 + ly) * Cn + cch] = v;
    }
}

extern "C" void kernel_launch(void* const* d_in, const int* in_sizes, int n_in,
                              void* d_out, int out_size) {
    const float* x    = (const float*)d_in[0];
    const float* Wqkv = (const float*)d_in[1];
    const float* Wout = (const float*)d_in[2];
    const float* bout = (const float*)d_in[3];
    const float* gnw  = (const float*)d_in[4];
    const float* gnb  = (const float*)d_in[5];
    float* out = (float*)d_out;

    cudaFuncSetAttribute(k_qkv_mma, cudaFuncAttributeMaxDynamicSharedMemorySize, SM_TOT);
    cudaFuncSetAttribute(k_out_mma, cudaFuncAttributeMaxDynamicSharedMemorySize, SM_TOT);

    k_zero<<<128, 256>>>();
    k_qkv_mma<<<(Bn * Ln) / 256, 256, SM_TOT>>>(x, Wqkv);
    k_ctx<<<dim3(Bn * Hn, 16), 256>>>();
    k_A<<<dim3(64, Bn), 256>>>(Wout);
    k_out_mma<<<(Bn * Ln) / 256, 256, SM_TOT>>>(bout);
    k_norm<<<dim3(Ln / 32, Cn / 32, Bn), dim3(32, 8)>>>(gnw, gnb, out);
}

// round 12
// speedup vs baseline: 1.7906x; 1.2436x over previous
#include <cuda_runtime.h>
#include <cuda_fp16.h>
#include <cstdint>

#define Bn 8
#define Ln 16384
#define Cn 128
#define Hn 4
#define Dn 32

// ---- scratch (device globals; no allocation allowed) ----
__device__ float g_kv[(size_t)Bn*256*Ln];        // [b, ch, l]: ch 0..127 = exp(k), 128..255 = v
__device__ __half g_qb[(size_t)Bn*Ln*Cn];        // softmaxed q, fp16, [b, l, c]
__device__ float g_o[(size_t)Bn*Cn*Ln];          // pre-norm output [b, c, l]
__device__ float g_ctx[Bn*Hn*Dn*Dn];
__device__ float g_Z[Bn*Hn*Dn];
__device__ __half g_Ah[Bn*Cn*Cn];                // folded W_out@blockdiag(ctx), fp16 hi
__device__ __half g_Al[Bn*Cn*Cn];                // fp16 lo (residual)
__device__ float g_bsum[Bn];
__device__ float g_bsq[Bn];

// ---- SMEM layout (bytes). fp16 tiles, row pitch 136 B (68 words). ----
#define PW32 68
#define X_S 0                 // data tile (single fp16): 256 rows * 272B = 69632
#define W_H 69632             // weight hi: 128 rows * 272B = 34816
#define W_L 104448            // weight lo
#define SM_TOT 139264

// fp16 hi/lo split of a float pair -> packed half2 words
__device__ __forceinline__ void split2h(float a, float b, uint32_t& hi, uint32_t& lo) {
    __half2 hp = __floats2half2_rn(a, b);
    hi = *(uint32_t*)&hp;
    __half2 lp = __floats2half2_rn(a - __half2float(hp.x), b - __half2float(hp.y));
    lo = *(uint32_t*)&lp;
}
__device__ __forceinline__ uint32_t pack2h(float a, float b) {
    __half2 hp = __floats2half2_rn(a, b);
    return *(uint32_t*)&hp;
}

__device__ __forceinline__ void mma_f16(float* c, const uint32_t* a, const uint32_t* b) {
    asm volatile(
        "mma.sync.aligned.m16n8k16.row.col.f32.f16.f16.f32 "
        "{%0,%1,%2,%3}, {%4,%5,%6,%7}, {%8,%9}, {%0,%1,%2,%3};"
        : "+f"(c[0]), "+f"(c[1]), "+f"(c[2]), "+f"(c[3])
        : "r"(a[0]), "r"(a[1]), "r"(a[2]), "r"(a[3]), "r"(b[0]), "r"(b[1]));
}

// 2-pass hi/lo GEMM core: acc += (Whi + Wlo)(128xK) x Xsingle(K x N slice)
// Warp tile 64x64: mf 0..3 (16 rows each), nf 0..7 (8 cols each).
__device__ __forceinline__ void gemm2(const char* smem, float (*acc)[8][4],
                                      int WM, int WN, int g, int t) {
    for (int cb = 0; cb < 2; cb++) {
        const uint32_t* A32 = (const uint32_t*)(smem + (cb ? W_L : W_H));
        const uint32_t* B32 = (const uint32_t*)(smem + X_S);
#pragma unroll
        for (int ks = 0; ks < 8; ks++) {
            int ko = ks * 8 + t;
            uint32_t a[4][4], bb[8][2];
#pragma unroll
            for (int mf = 0; mf < 4; mf++) {
                int r = (WM + mf * 16 + g) * PW32 + ko;
                a[mf][0] = A32[r];
                a[mf][1] = A32[r + 8 * PW32];
                a[mf][2] = A32[r + 4];
                a[mf][3] = A32[r + 8 * PW32 + 4];
            }
#pragma unroll
            for (int nf = 0; nf < 8; nf++) {
                int r = (WN + nf * 8 + g) * PW32 + ko;
                bb[nf][0] = B32[r];
                bb[nf][1] = B32[r + 4];
            }
#pragma unroll
            for (int mf = 0; mf < 4; mf++)
#pragma unroll
                for (int nf = 0; nf < 8; nf++)
                    mma_f16(acc[mf][nf], a[mf], bb[nf]);
        }
    }
}

// ---- K0: zero accumulators (graph replays!) ----
__global__ void k_zero() {
    int i = blockIdx.x * 256 + threadIdx.x;
    if (i < Bn*Hn*Dn*Dn) g_ctx[i] = 0.f;
    if (i < Bn*Hn*Dn)    g_Z[i]   = 0.f;
    if (i < Bn)          { g_bsum[i] = 0.f; g_bsq[i] = 0.f; }
}

// ======== K1: HMMA QKV GEMM + fused q-softmax + exp(k) ========
// CTA: 256 positions x 3 m-tiles of 128 out channels, K=128.
__global__ __launch_bounds__(256, 1) void k_qkv_mma(const float* __restrict__ x,
                                                    const float* __restrict__ Wqkv) {
    extern __shared__ __align__(16) char smem[];
    int tid = threadIdx.x, wid = tid >> 5, lid = tid & 31;
    int g = lid >> 2, t = lid & 3;
    int WM = (wid & 1) * 64, WN = (wid >> 1) * 64;
    int p0 = blockIdx.x * 256;
    int b = p0 >> 14, l0 = p0 & (Ln - 1);
    uint32_t* XS = (uint32_t*)(smem + X_S);
    uint32_t* WHp = (uint32_t*)(smem + W_H);
    uint32_t* WLp = (uint32_t*)(smem + W_L);

    // ---- load X tile: 256 pos x 128 ch, single fp16 ----
    const float4* x4 = (const float4*)(x + (size_t)p0 * Cn);
#pragma unroll
    for (int it = 0; it < 32; it++) {
        int f = it * 256 + tid, row = f >> 5, u = f & 31;
        float4 v = x4[f];
        int wb = row * PW32 + u * 2;
        XS[wb]     = pack2h(v.x, v.y);
        XS[wb + 1] = pack2h(v.z, v.w);
    }

    for (int mt = 0; mt < 3; mt++) {
        // ---- load + split W m-tile: 128 x 128, fp16 hi/lo ----
        const float4* w4 = (const float4*)(Wqkv + (size_t)mt * Cn * Cn);
#pragma unroll
        for (int it = 0; it < 16; it++) {
            int f = it * 256 + tid, row = f >> 5, u = f & 31;
            float4 v = w4[f];
            uint32_t h0, l0w, h1, l1w;
            split2h(v.x, v.y, h0, l0w);
            split2h(v.z, v.w, h1, l1w);
            int wb = row * PW32 + u * 2;
            WHp[wb] = h0; WHp[wb + 1] = h1;
            WLp[wb] = l0w; WLp[wb + 1] = l1w;
        }
        __syncthreads();

        float acc[4][8][4];
#pragma unroll
        for (int mf = 0; mf < 4; mf++)
#pragma unroll
            for (int nf = 0; nf < 8; nf++)
#pragma unroll
                for (int q = 0; q < 4; q++) acc[mf][nf][q] = 0.f;

        gemm2(smem, acc, WM, WN, g, t);
        __syncthreads();

        if (mt == 0) {
            // q: stage transposed in W region (2 rounds of 128 positions), softmax
            float* qs = (float*)(smem + W_H);
            for (int r = 0; r < 2; r++) {
                if ((WN >> 7) == r) {
#pragma unroll
                    for (int mf = 0; mf < 4; mf++)
#pragma unroll
                        for (int nf = 0; nf < 8; nf++) {
                            int m = WM + mf * 16 + g;
                            int nl = WN + nf * 8 + 2 * t - r * 128;
                            qs[nl * 129 + m]           = acc[mf][nf][0];
                            qs[(nl + 1) * 129 + m]     = acc[mf][nf][1];
                            qs[nl * 129 + m + 8]       = acc[mf][nf][2];
                            qs[(nl + 1) * 129 + m + 8] = acc[mf][nf][3];
                        }
                }
                __syncthreads();
                int pos = tid >> 1, hb = (tid & 1) * 64;
                size_t gq = ((size_t)(b * Ln + l0 + r * 128 + pos)) * Cn + hb;
#pragma unroll
                for (int hh = 0; hh < 2; hh++) {
                    float vv[32]; float mx = -1e30f;
#pragma unroll
                    for (int d = 0; d < 32; d++) {
                        vv[d] = qs[pos * 129 + hb + hh * 32 + d];
                        mx = fmaxf(mx, vv[d]);
                    }
                    float s = 0.f;
#pragma unroll
                    for (int d = 0; d < 32; d++) { vv[d] = __expf(vv[d] - mx); s += vv[d]; }
                    float inv = 0.17677669529663689f / s;   // d^-0.5 / s
                    uint32_t ph[16];
#pragma unroll
                    for (int d2 = 0; d2 < 16; d2++)
                        ph[d2] = pack2h(vv[2 * d2] * inv, vv[2 * d2 + 1] * inv);
                    uint4* dh = (uint4*)(g_qb + gq + hh * 32);
#pragma unroll
                    for (int w = 0; w < 4; w++)
                        dh[w] = make_uint4(ph[4*w], ph[4*w+1], ph[4*w+2], ph[4*w+3]);
                }
                __syncthreads();
            }
        } else {
            // k -> exp(k); v -> raw; channel-major [b, ch, l]
            float* gk = g_kv + ((size_t)(b * 256 + (mt - 1) * 128)) * Ln + l0;
#pragma unroll
            for (int mf = 0; mf < 4; mf++)
#pragma unroll
                for (int nf = 0; nf < 8; nf++) {
                    int m = WM + mf * 16 + g;
                    int n0 = WN + nf * 8 + 2 * t;
                    float c0 = acc[mf][nf][0], c1 = acc[mf][nf][1];
                    float c2 = acc[mf][nf][2], c3 = acc[mf][nf][3];
                    if (mt == 1) {
                        c0 = __expf(c0); c1 = __expf(c1);
                        c2 = __expf(c2); c3 = __expf(c3);
                    }
                    *(float2*)(gk + (size_t)m * Ln + n0)       = make_float2(c0, c1);
                    *(float2*)(gk + (size_t)(m + 8) * Ln + n0) = make_float2(c2, c3);
                }
            __syncthreads();
        }
    }
}

// ---- K3: context[bh,c,d] += sum_j ek[c,j] v[d,j]; Z[bh,c] += sum_j ek[c,j] ----
__global__ __launch_bounds__(256) void k_ctx() {
    __shared__ float ks[32][33];
    __shared__ float vs[32][33];
    int t = threadIdx.x;
    int bh = blockIdx.x;
    int b = bh >> 2, h = bh & 3;
    const float* kbase = g_kv + (size_t)(b * 256 + h * Dn) * Ln;
    const float* vbase = g_kv + (size_t)(b * 256 + 128 + h * Dn) * Ln;
    int j0base = blockIdx.y * 1024;
    int g = t >> 6;
    int w = t & 63;
    int c4 = (w >> 3) * 4;
    int d4 = (w & 7) * 4;
    float acc[4][4];
#pragma unroll
    for (int i = 0; i < 4; i++)
#pragma unroll
        for (int k = 0; k < 4; k++) acc[i][k] = 0.f;
    float zl = 0.f;

    for (int jb = 0; jb < 32; jb++) {
        int j0 = j0base + jb * 32;
#pragma unroll
        for (int it = 0; it < 4; it++) {
            int idx = it * 256 + t;
            int c = idx >> 5, j = idx & 31;
            ks[c][j] = kbase[(size_t)c * Ln + j0 + j];
            vs[c][j] = vbase[(size_t)c * Ln + j0 + j];
        }
        __syncthreads();
#pragma unroll
        for (int jj = 0; jj < 8; jj++) {
            int j = g * 8 + jj;
            float e[4], v[4];
#pragma unroll
            for (int i = 0; i < 4; i++) { e[i] = ks[c4 + i][j]; v[i] = vs[d4 + i][j]; }
#pragma unroll
            for (int i = 0; i < 4; i++)
#pragma unroll
                for (int k = 0; k < 4; k++) acc[i][k] += e[i] * v[k];
        }
        if (w < 32) {
#pragma unroll
            for (int jj = 0; jj < 8; jj++) zl += ks[w][g * 8 + jj];
        }
        __syncthreads();
    }
#pragma unroll
    for (int i = 0; i < 4; i++)
#pragma unroll
        for (int k = 0; k < 4; k++)
            atomicAdd(&g_ctx[bh * 1024 + (c4 + i) * 32 + d4 + k], acc[i][k]);
    if (w < 32) atomicAdd(&g_Z[bh * 32 + w], zl);
}

// ---- K4: A_b = Wout @ blockdiag(ctx/Z), fp16 hi/lo. One output per thread. ----
// grid (64, Bn): blockIdx.y = b, 256 outputs per block (2 o-rows x 128 cols).
__global__ __launch_bounds__(256) void k_A(const float* __restrict__ Wout) {
    __shared__ float rZ[128];
    int t = threadIdx.x;
    int b = blockIdx.y;
    if (t < 128) rZ[t] = 1.f / g_Z[b * 128 + t];
    __syncthreads();
    int idx = blockIdx.x * 256 + t;        // 0..16383
    int o = idx >> 7, jcol = idx & 127;
    int h = jcol >> 5, d = jcol & 31;
    const float* wrow = Wout + o * Cn + h * Dn;         // warp-uniform (broadcast)
    const float* cb = g_ctx + b * 4096 + h * 1024 + d;  // lanes d coalesce
    const float* rz = rZ + h * Dn;
    float s = 0.f;
#pragma unroll
    for (int c = 0; c < 32; c++) s += wrow[c] * rz[c] * cb[c * 32];
    __half hb = __float2half(s);
    g_Ah[b * Cn * Cn + idx] = hb;
    g_Al[b * Cn * Cn + idx] = __float2half(s - __half2float(hb));
}

// ======== K5: HMMA out GEMM: o = A_b @ q + bias; accumulate sum/sumsq ========
__global__ __launch_bounds__(256, 1) void k_out_mma(const float* __restrict__ bout) {
    extern __shared__ __align__(16) char smem[];
    int tid = threadIdx.x, wid = tid >> 5, lid = tid & 31;
    int g = lid >> 2, t = lid & 3;
    int WM = (wid & 1) * 64, WN = (wid >> 1) * 64;
    int p0 = blockIdx.x * 256;
    int b = p0 >> 14, l0 = p0 & (Ln - 1);
    uint32_t* XS = (uint32_t*)(smem + X_S);
    uint32_t* WHp = (uint32_t*)(smem + W_H);
    uint32_t* WLp = (uint32_t*)(smem + W_L);

    // Q tile (single fp16, [l][c] K-major rows of 256B)
    const uint4* q4 = (const uint4*)(g_qb + (size_t)p0 * Cn);
#pragma unroll
    for (int it = 0; it < 16; it++) {
        int f = it * 256 + tid, row = f >> 4, u = f & 15;
        *(uint4*)(XS + row * PW32 + u * 4) = q4[f];
    }
    // A tiles (fp16 hi/lo)
    const uint4* ah4 = (const uint4*)(g_Ah + (size_t)b * Cn * Cn);
    const uint4* al4 = (const uint4*)(g_Al + (size_t)b * Cn * Cn);
#pragma unroll
    for (int it = 0; it < 8; it++) {
        int f = it * 256 + tid, row = f >> 4, u = f & 15;
        *(uint4*)(WHp + row * PW32 + u * 4) = ah4[f];
        *(uint4*)(WLp + row * PW32 + u * 4) = al4[f];
    }
    __syncthreads();

    float acc[4][8][4];
#pragma unroll
    for (int mf = 0; mf < 4; mf++)
#pragma unroll
        for (int nf = 0; nf < 8; nf++)
#pragma unroll
            for (int q = 0; q < 4; q++) acc[mf][nf][q] = 0.f;

    gemm2(smem, acc, WM, WN, g, t);
    __syncthreads();

    float lsum = 0.f, lsq = 0.f;
    float* go = g_o + ((size_t)b * Cn) * Ln + l0;
#pragma unroll
    for (int mf = 0; mf < 4; mf++) {
        int m = WM + mf * 16 + g;
        float b0v = bout[m], b1v = bout[m + 8];
#pragma unroll
        for (int nf = 0; nf < 8; nf++) {
            int n0 = WN + nf * 8 + 2 * t;
            float c0 = acc[mf][nf][0] + b0v, c1 = acc[mf][nf][1] + b0v;
            float c2 = acc[mf][nf][2] + b1v, c3 = acc[mf][nf][3] + b1v;
            lsum += c0 + c1 + c2 + c3;
            lsq  += c0 * c0 + c1 * c1 + c2 * c2 + c3 * c3;
            *(float2*)(go + (size_t)m * Ln + n0)       = make_float2(c0, c1);
            *(float2*)(go + (size_t)(m + 8) * Ln + n0) = make_float2(c2, c3);
        }
    }
    float* red = (float*)(smem + W_H);
    red[tid] = lsum; __syncthreads();
    for (int s = 128; s > 0; s >>= 1) { if (tid < s) red[tid] += red[tid + s]; __syncthreads(); }
    if (tid == 0) atomicAdd(&g_bsum[b], red[0]);
    __syncthreads();
    red[tid] = lsq; __syncthreads();
    for (int s = 128; s > 0; s >>= 1) { if (tid < s) red[tid] += red[tid + s]; __syncthreads(); }
    if (tid == 0) atomicAdd(&g_bsq[b], red[0]);
}

// ---- K6: GroupNorm(1,C) + transpose to [b, l, c] ----
__global__ void k_norm(const float* __restrict__ gnw, const float* __restrict__ gnb,
                       float* __restrict__ out) {
    __shared__ float tile[32][33];
    int b  = blockIdx.z;
    int c0 = blockIdx.y * 32;
    int l0 = blockIdx.x * 32;
    const float n = 2097152.0f;           // C*L
    float mean = g_bsum[b] / n;
    float var  = g_bsq[b] / n - mean * mean;
    float rstd = rsqrtf(var + 1e-5f);
    int tx = threadIdx.x, ty = threadIdx.y;
#pragma unroll
    for (int r = 0; r < 4; r++) {
        int cy = ty * 4 + r;
        tile[cy][tx] = g_o[(size_t)(b * Cn + c0 + cy) * Ln + l0 + tx];
    }
    __syncthreads();
#pragma unroll
    for (int r = 0; r < 4; r++) {
        int ly = ty * 4 + r;
        int cch = c0 + tx;
        float v = (tile[tx][ly] - mean) * rstd * gnw[cch] + gnb[cch];
        out[(size_t)(b * Ln + l0 + ly) * Cn + cch] = v;
    }
}

extern "C" void kernel_launch(void* const* d_in, const int* in_sizes, int n_in,
                              void* d_out, int out_size) {
    const float* x    = (const float*)d_in[0];
    const float* Wqkv = (const float*)d_in[1];
    const float* Wout = (const float*)d_in[2];
    const float* bout = (const float*)d_in[3];
    const float* gnw  = (const float*)d_in[4];
    const float* gnb  = (const float*)d_in[5];
    float* out = (float*)d_out;

    cudaFuncSetAttribute(k_qkv_mma, cudaFuncAttributeMaxDynamicSharedMemorySize, SM_TOT);
    cudaFuncSetAttribute(k_out_mma, cudaFuncAttributeMaxDynamicSharedMemorySize, SM_TOT);

    k_zero<<<128, 256>>>();
    k_qkv_mma<<<(Bn * Ln) / 256, 256, SM_TOT>>>(x, Wqkv);
    k_ctx<<<dim3(Bn * Hn, 16), 256>>>();
    k_A<<<dim3(64, Bn), 256>>>(Wout);
    k_out_mma<<<(Bn * Ln) / 256, 256, SM_TOT>>>(bout);
    k_norm<<<dim3(Ln / 32, Cn / 32, Bn), dim3(32, 8)>>>(gnw, gnb, out);
}

// round 15
// speedup vs baseline: 1.8007x; 1.0056x over previous
#include <cuda_runtime.h>
#include <cuda_fp16.h>
#include <cstdint>

#define Bn 8
#define Ln 16384
#define Cn 128
#define Hn 4
#define Dn 32

// ---- scratch (device globals; no allocation allowed) ----
__device__ __half g_kv[(size_t)Bn*256*Ln];       // [b, ch, l]: ch 0..127 = exp(k), 128..255 = v (fp16)
__device__ __half g_qb[(size_t)Bn*Ln*Cn];        // softmaxed q, fp16, [b, l, c]
__device__ float g_o[(size_t)Bn*Cn*Ln];          // pre-norm output [b, c, l]
__device__ float g_ctx[Bn*Hn*Dn*Dn];
__device__ float g_Z[Bn*Hn*Dn];
__device__ __half g_Ah[Bn*Cn*Cn];                // folded W_out@blockdiag(ctx), fp16 hi
__device__ __half g_Al[Bn*Cn*Cn];                // fp16 lo (residual)
__device__ float g_bsum[Bn];
__device__ float g_bsq[Bn];

// ---- SMEM layout (bytes). fp16 tiles, row pitch 136 B (68 words). ----
#define PW32 68
#define X_S 0                 // data tile (single fp16): 256 rows * 272B = 69632
#define W_H 69632             // weight hi: 128 rows * 272B = 34816
#define W_L 104448            // weight lo
#define SM_TOT 139264

// fp16 hi/lo split of a float pair -> packed half2 words
__device__ __forceinline__ void split2h(float a, float b, uint32_t& hi, uint32_t& lo) {
    __half2 hp = __floats2half2_rn(a, b);
    hi = *(uint32_t*)&hp;
    __half2 lp = __floats2half2_rn(a - __half2float(hp.x), b - __half2float(hp.y));
    lo = *(uint32_t*)&lp;
}
__device__ __forceinline__ uint32_t pack2h(float a, float b) {
    __half2 hp = __floats2half2_rn(a, b);
    return *(uint32_t*)&hp;
}

__device__ __forceinline__ void mma_f16(float* c, const uint32_t* a, const uint32_t* b) {
    asm volatile(
        "mma.sync.aligned.m16n8k16.row.col.f32.f16.f16.f32 "
        "{%0,%1,%2,%3}, {%4,%5,%6,%7}, {%8,%9}, {%0,%1,%2,%3};"
        : "+f"(c[0]), "+f"(c[1]), "+f"(c[2]), "+f"(c[3])
        : "r"(a[0]), "r"(a[1]), "r"(a[2]), "r"(a[3]), "r"(b[0]), "r"(b[1]));
}

// 2-pass hi/lo GEMM core: acc += (Whi + Wlo)(128xK) x Xsingle(K x N slice)
// Warp tile 64x64: mf 0..3 (16 rows each), nf 0..7 (8 cols each).
__device__ __forceinline__ void gemm2(const char* smem, float (*acc)[8][4],
                                      int WM, int WN, int g, int t) {
    for (int cb = 0; cb < 2; cb++) {
        const uint32_t* A32 = (const uint32_t*)(smem + (cb ? W_L : W_H));
        const uint32_t* B32 = (const uint32_t*)(smem + X_S);
#pragma unroll
        for (int ks = 0; ks < 8; ks++) {
            int ko = ks * 8 + t;
            uint32_t a[4][4], bb[8][2];
#pragma unroll
            for (int mf = 0; mf < 4; mf++) {
                int r = (WM + mf * 16 + g) * PW32 + ko;
                a[mf][0] = A32[r];
                a[mf][1] = A32[r + 8 * PW32];
                a[mf][2] = A32[r + 4];
                a[mf][3] = A32[r + 8 * PW32 + 4];
            }
#pragma unroll
            for (int nf = 0; nf < 8; nf++) {
                int r = (WN + nf * 8 + g) * PW32 + ko;
                bb[nf][0] = B32[r];
                bb[nf][1] = B32[r + 4];
            }
#pragma unroll
            for (int mf = 0; mf < 4; mf++)
#pragma unroll
                for (int nf = 0; nf < 8; nf++)
                    mma_f16(acc[mf][nf], a[mf], bb[nf]);
        }
    }
}

// ---- K0: zero accumulators (graph replays!) ----
__global__ void k_zero() {
    int i = blockIdx.x * 256 + threadIdx.x;
    if (i < Bn*Hn*Dn*Dn) g_ctx[i] = 0.f;
    if (i < Bn*Hn*Dn)    g_Z[i]   = 0.f;
    if (i < Bn)          { g_bsum[i] = 0.f; g_bsq[i] = 0.f; }
}

// ======== K1: HMMA QKV GEMM + fused q-softmax + exp(k) ========
// CTA: 256 positions x 3 m-tiles of 128 out channels, K=128.
__global__ __launch_bounds__(256, 1) void k_qkv_mma(const float* __restrict__ x,
                                                    const float* __restrict__ Wqkv) {
    extern __shared__ __align__(16) char smem[];
    int tid = threadIdx.x, wid = tid >> 5, lid = tid & 31;
    int g = lid >> 2, t = lid & 3;
    int WM = (wid & 1) * 64, WN = (wid >> 1) * 64;
    int p0 = blockIdx.x * 256;
    int b = p0 >> 14, l0 = p0 & (Ln - 1);
    uint32_t* XS = (uint32_t*)(smem + X_S);
    uint32_t* WHp = (uint32_t*)(smem + W_H);
    uint32_t* WLp = (uint32_t*)(smem + W_L);

    // ---- load X tile: 256 pos x 128 ch, single fp16 ----
    const float4* x4 = (const float4*)(x + (size_t)p0 * Cn);
#pragma unroll
    for (int it = 0; it < 32; it++) {
        int f = it * 256 + tid, row = f >> 5, u = f & 31;
        float4 v = x4[f];
        int wb = row * PW32 + u * 2;
        XS[wb]     = pack2h(v.x, v.y);
        XS[wb + 1] = pack2h(v.z, v.w);
    }

    for (int mt = 0; mt < 3; mt++) {
        // ---- load + split W m-tile: 128 x 128, fp16 hi/lo ----
        const float4* w4 = (const float4*)(Wqkv + (size_t)mt * Cn * Cn);
#pragma unroll
        for (int it = 0; it < 16; it++) {
            int f = it * 256 + tid, row = f >> 5, u = f & 31;
            float4 v = w4[f];
            uint32_t h0, l0w, h1, l1w;
            split2h(v.x, v.y, h0, l0w);
            split2h(v.z, v.w, h1, l1w);
            int wb = row * PW32 + u * 2;
            WHp[wb] = h0; WHp[wb + 1] = h1;
            WLp[wb] = l0w; WLp[wb + 1] = l1w;
        }
        __syncthreads();

        float acc[4][8][4];
#pragma unroll
        for (int mf = 0; mf < 4; mf++)
#pragma unroll
            for (int nf = 0; nf < 8; nf++)
#pragma unroll
                for (int q = 0; q < 4; q++) acc[mf][nf][q] = 0.f;

        gemm2(smem, acc, WM, WN, g, t);
        __syncthreads();

        if (mt == 0) {
            // q: stage transposed in W region (2 rounds of 128 positions), softmax
            float* qs = (float*)(smem + W_H);
            for (int r = 0; r < 2; r++) {
                if ((WN >> 7) == r) {
#pragma unroll
                    for (int mf = 0; mf < 4; mf++)
#pragma unroll
                        for (int nf = 0; nf < 8; nf++) {
                            int m = WM + mf * 16 + g;
                            int nl = WN + nf * 8 + 2 * t - r * 128;
                            qs[nl * 129 + m]           = acc[mf][nf][0];
                            qs[(nl + 1) * 129 + m]     = acc[mf][nf][1];
                            qs[nl * 129 + m + 8]       = acc[mf][nf][2];
                            qs[(nl + 1) * 129 + m + 8] = acc[mf][nf][3];
                        }
                }
                __syncthreads();
                int pos = tid >> 1, hb = (tid & 1) * 64;
                size_t gq = ((size_t)(b * Ln + l0 + r * 128 + pos)) * Cn + hb;
#pragma unroll
                for (int hh = 0; hh < 2; hh++) {
                    float vv[32]; float mx = -1e30f;
#pragma unroll
                    for (int d = 0; d < 32; d++) {
                        vv[d] = qs[pos * 129 + hb + hh * 32 + d];
                        mx = fmaxf(mx, vv[d]);
                    }
                    float s = 0.f;
#pragma unroll
                    for (int d = 0; d < 32; d++) { vv[d] = __expf(vv[d] - mx); s += vv[d]; }
                    float inv = 0.17677669529663689f / s;   // d^-0.5 / s
                    uint32_t ph[16];
#pragma unroll
                    for (int d2 = 0; d2 < 16; d2++)
                        ph[d2] = pack2h(vv[2 * d2] * inv, vv[2 * d2 + 1] * inv);
                    uint4* dh = (uint4*)(g_qb + gq + hh * 32);
#pragma unroll
                    for (int w = 0; w < 4; w++)
                        dh[w] = make_uint4(ph[4*w], ph[4*w+1], ph[4*w+2], ph[4*w+3]);
                }
                __syncthreads();
            }
        } else {
            // k -> exp(k); v -> raw; channel-major [b, ch, l], fp16
            __half* gk = g_kv + ((size_t)(b * 256 + (mt - 1) * 128)) * Ln + l0;
#pragma unroll
            for (int mf = 0; mf < 4; mf++)
#pragma unroll
                for (int nf = 0; nf < 8; nf++) {
                    int m = WM + mf * 16 + g;
                    int n0 = WN + nf * 8 + 2 * t;
                    float c0 = acc[mf][nf][0], c1 = acc[mf][nf][1];
                    float c2 = acc[mf][nf][2], c3 = acc[mf][nf][3];
                    if (mt == 1) {
                        c0 = __expf(c0); c1 = __expf(c1);
                        c2 = __expf(c2); c3 = __expf(c3);
                    }
                    *(uint32_t*)(gk + (size_t)m * Ln + n0)       = pack2h(c0, c1);
                    *(uint32_t*)(gk + (size_t)(m + 8) * Ln + n0) = pack2h(c2, c3);
                }
            __syncthreads();
        }
    }
}

// ---- K3: context[bh,c,d] += sum_j ek[c,j] v[d,j]; Z[bh,c] += sum_j ek[c,j] ----
// fp16 inputs, half2 smem tiles, 4x4 register tiling.
__global__ __launch_bounds__(256) void k_ctx() {
    __shared__ __half2 ks[32][17];
    __shared__ __half2 vs[32][17];
    int t = threadIdx.x;
    int bh = blockIdx.x;
    int b = bh >> 2, h = bh & 3;
    const __half* kbase = g_kv + (size_t)(b * 256 + h * Dn) * Ln;
    const __half* vbase = g_kv + (size_t)(b * 256 + 128 + h * Dn) * Ln;
    int j0base = blockIdx.y * 1024;
    int g = t >> 6;             // j subgroup 0..3 (8 j = 4 half2 each)
    int w = t & 63;
    int c4 = (w >> 3) * 4;
    int d4 = (w & 7) * 4;
    float acc[4][4];
#pragma unroll
    for (int i = 0; i < 4; i++)
#pragma unroll
        for (int k = 0; k < 4; k++) acc[i][k] = 0.f;
    float zl = 0.f;

    for (int jb = 0; jb < 32; jb++) {
        int j0 = j0base + jb * 32;
#pragma unroll
        for (int it = 0; it < 2; it++) {
            int idx = it * 256 + t;          // 0..511
            int c = idx >> 4, u = idx & 15;  // 32 rows x 16 half2 words
            ks[c][u] = ((const __half2*)(kbase + (size_t)c * Ln + j0))[u];
            vs[c][u] = ((const __half2*)(vbase + (size_t)c * Ln + j0))[u];
        }
        __syncthreads();
#pragma unroll
        for (int jj = 0; jj < 4; jj++) {
            int j2 = g * 4 + jj;
            float2 e[4], v[4];
#pragma unroll
            for (int i = 0; i < 4; i++) {
                e[i] = __half22float2(ks[c4 + i][j2]);
                v[i] = __half22float2(vs[d4 + i][j2]);
            }
#pragma unroll
            for (int i = 0; i < 4; i++)
#pragma unroll
                for (int k = 0; k < 4; k++)
                    acc[i][k] += e[i].x * v[k].x + e[i].y * v[k].y;
        }
        if (w < 32) {
#pragma unroll
            for (int jj = 0; jj < 4; jj++) {
                float2 z2 = __half22float2(ks[w][g * 4 + jj]);
                zl += z2.x + z2.y;
            }
        }
        __syncthreads();
    }
#pragma unroll
    for (int i = 0; i < 4; i++)
#pragma unroll
        for (int k = 0; k < 4; k++)
            atomicAdd(&g_ctx[bh * 1024 + (c4 + i) * 32 + d4 + k], acc[i][k]);
    if (w < 32) atomicAdd(&g_Z[bh * 32 + w], zl);
}

// ---- K4: A_b = Wout @ blockdiag(ctx/Z), fp16 hi/lo. One output per thread. ----
// grid (64, Bn): blockIdx.y = b, 256 outputs per block (2 o-rows x 128 cols).
__global__ __launch_bounds__(256) void k_A(const float* __restrict__ Wout) {
    __shared__ float rZ[128];
    int t = threadIdx.x;
    int b = blockIdx.y;
    if (t < 128) rZ[t] = 1.f / g_Z[b * 128 + t];
    __syncthreads();
    int idx = blockIdx.x * 256 + t;        // 0..16383
    int o = idx >> 7, jcol = idx & 127;
    int h = jcol >> 5, d = jcol & 31;
    const float* wrow = Wout + o * Cn + h * Dn;         // warp-uniform (broadcast)
    const float* cb = g_ctx + b * 4096 + h * 1024 + d;  // lanes d coalesce
    const float* rz = rZ + h * Dn;
    float s = 0.f;
#pragma unroll
    for (int c = 0; c < 32; c++) s += wrow[c] * rz[c] * cb[c * 32];
    __half hb = __float2half(s);
    g_Ah[b * Cn * Cn + idx] = hb;
    g_Al[b * Cn * Cn + idx] = __float2half(s - __half2float(hb));
}

// ======== K5: HMMA out GEMM: o = A_b @ q + bias; accumulate sum/sumsq ========
__global__ __launch_bounds__(256, 1) void k_out_mma(const float* __restrict__ bout) {
    extern __shared__ __align__(16) char smem[];
    int tid = threadIdx.x, wid = tid >> 5, lid = tid & 31;
    int g = lid >> 2, t = lid & 3;
    int WM = (wid & 1) * 64, WN = (wid >> 1) * 64;
    int p0 = blockIdx.x * 256;
    int b = p0 >> 14, l0 = p0 & (Ln - 1);
    uint32_t* XS = (uint32_t*)(smem + X_S);
    uint32_t* WHp = (uint32_t*)(smem + W_H);
    uint32_t* WLp = (uint32_t*)(smem + W_L);

    // Q tile (single fp16, [l][c] K-major rows of 256B)
    const uint4* q4 = (const uint4*)(g_qb + (size_t)p0 * Cn);
#pragma unroll
    for (int it = 0; it < 16; it++) {
        int f = it * 256 + tid, row = f >> 4, u = f & 15;
        *(uint4*)(XS + row * PW32 + u * 4) = q4[f];
    }
    // A tiles (fp16 hi/lo)
    const uint4* ah4 = (const uint4*)(g_Ah + (size_t)b * Cn * Cn);
    const uint4* al4 = (const uint4*)(g_Al + (size_t)b * Cn * Cn);
#pragma unroll
    for (int it = 0; it < 8; it++) {
        int f = it * 256 + tid, row = f >> 4, u = f & 15;
        *(uint4*)(WHp + row * PW32 + u * 4) = ah4[f];
        *(uint4*)(WLp + row * PW32 + u * 4) = al4[f];
    }
    __syncthreads();

    float acc[4][8][4];
#pragma unroll
    for (int mf = 0; mf < 4; mf++)
#pragma unroll
        for (int nf = 0; nf < 8; nf++)
#pragma unroll
            for (int q = 0; q < 4; q++) acc[mf][nf][q] = 0.f;

    gemm2(smem, acc, WM, WN, g, t);
    __syncthreads();

    float lsum = 0.f, lsq = 0.f;
    float* go = g_o + ((size_t)b * Cn) * Ln + l0;
#pragma unroll
    for (int mf = 0; mf < 4; mf++) {
        int m = WM + mf * 16 + g;
        float b0v = bout[m], b1v = bout[m + 8];
#pragma unroll
        for (int nf = 0; nf < 8; nf++) {
            int n0 = WN + nf * 8 + 2 * t;
            float c0 = acc[mf][nf][0] + b0v, c1 = acc[mf][nf][1] + b0v;
            float c2 = acc[mf][nf][2] + b1v, c3 = acc[mf][nf][3] + b1v;
            lsum += c0 + c1 + c2 + c3;
            lsq  += c0 * c0 + c1 * c1 + c2 * c2 + c3 * c3;
            *(float2*)(go + (size_t)m * Ln + n0)       = make_float2(c0, c1);
            *(float2*)(go + (size_t)(m + 8) * Ln + n0) = make_float2(c2, c3);
        }
    }
    float* red = (float*)(smem + W_H);
    red[tid] = lsum; __syncthreads();
    for (int s = 128; s > 0; s >>= 1) { if (tid < s) red[tid] += red[tid + s]; __syncthreads(); }
    if (tid == 0) atomicAdd(&g_bsum[b], red[0]);
    __syncthreads();
    red[tid] = lsq; __syncthreads();
    for (int s = 128; s > 0; s >>= 1) { if (tid < s) red[tid] += red[tid + s]; __syncthreads(); }
    if (tid == 0) atomicAdd(&g_bsq[b], red[0]);
}

// ---- K6: GroupNorm(1,C) + transpose to [b, l, c] ----
__global__ void k_norm(const float* __restrict__ gnw, const float* __restrict__ gnb,
                       float* __restrict__ out) {
    __shared__ float tile[32][33];
    int b  = blockIdx.z;
    int c0 = blockIdx.y * 32;
    int l0 = blockIdx.x * 32;
    const float n = 2097152.0f;           // C*L
    float mean = g_bsum[b] / n;
    float var  = g_bsq[b] / n - mean * mean;
    float rstd = rsqrtf(var + 1e-5f);
    int tx = threadIdx.x, ty = threadIdx.y;
#pragma unroll
    for (int r = 0; r < 4; r++) {
        int cy = ty * 4 + r;
        tile[cy][tx] = g_o[(size_t)(b * Cn + c0 + cy) * Ln + l0 + tx];
    }
    __syncthreads();
#pragma unroll
    for (int r = 0; r < 4; r++) {
        int ly = ty * 4 + r;
        int cch = c0 + tx;
        float v = (tile[tx][ly] - mean) * rstd * gnw[cch] + gnb[cch];
        out[(size_t)(b * Ln + l0 + ly) * Cn + cch] = v;
    }
}

extern "C" void kernel_launch(void* const* d_in, const int* in_sizes, int n_in,
                              void* d_out, int out_size) {
    const float* x    = (const float*)d_in[0];
    const float* Wqkv = (const float*)d_in[1];
    const float* Wout = (const float*)d_in[2];
    const float* bout = (const float*)d_in[3];
    const float* gnw  = (const float*)d_in[4];
    const float* gnb  = (const float*)d_in[5];
    float* out = (float*)d_out;

    cudaFuncSetAttribute(k_qkv_mma, cudaFuncAttributeMaxDynamicSharedMemorySize, SM_TOT);
    cudaFuncSetAttribute(k_out_mma, cudaFuncAttributeMaxDynamicSharedMemorySize, SM_TOT);

    k_zero<<<128, 256>>>();
    k_qkv_mma<<<(Bn * Ln) / 256, 256, SM_TOT>>>(x, Wqkv);
    k_ctx<<<dim3(Bn * Hn, 16), 256>>>();
    k_A<<<dim3(64, Bn), 256>>>(Wout);
    k_out_mma<<<(Bn * Ln) / 256, 256, SM_TOT>>>(bout);
    k_norm<<<dim3(Ln / 32, Cn / 32, Bn), dim3(32, 8)>>>(gnw, gnb, out);
}

// round 16
// speedup vs baseline: 1.9633x; 1.0903x over previous
#include <cuda_runtime.h>
#include <cuda_fp16.h>
#include <cstdint>

#define Bn 8
#define Ln 16384
#define Cn 128
#define Hn 4
#define Dn 32

// ---- scratch (device globals; no allocation allowed) ----
__device__ __half g_kv[(size_t)Bn*256*Ln];       // [b, ch, l]: ch 0..127 = exp(k), 128..255 = v (fp16)
__device__ __half g_qb[(size_t)Bn*Ln*Cn];        // softmaxed q, fp16, [b, l, c]
__device__ __half g_o[(size_t)Bn*Cn*Ln];         // pre-norm output [b, c, l] (fp16)
__device__ float g_ctx[Bn*Hn*Dn*Dn];
__device__ float g_Z[Bn*Hn*Dn];
__device__ __half g_Ah[Bn*Cn*Cn];                // folded W_out@blockdiag(ctx), fp16 hi
__device__ __half g_Al[Bn*Cn*Cn];                // fp16 lo (residual)
__device__ float g_bsum[Bn];
__device__ float g_bsq[Bn];

// ---- SMEM layout (bytes). fp16 tiles, row pitch 136 B (68 words). N-tile = 128. ----
#define PW32 68
#define X_S 0                 // data tile (single fp16): 128 rows * 272B = 34816
#define W_H 34816             // weight hi: 128 rows * 272B = 34816
#define W_L 69632             // weight lo
#define SM_TOT 104448         // 2 CTAs/SM (2x102KB < 228KB)

// fp16 hi/lo split of a float pair -> packed half2 words
__device__ __forceinline__ void split2h(float a, float b, uint32_t& hi, uint32_t& lo) {
    __half2 hp = __floats2half2_rn(a, b);
    hi = *(uint32_t*)&hp;
    __half2 lp = __floats2half2_rn(a - __half2float(hp.x), b - __half2float(hp.y));
    lo = *(uint32_t*)&lp;
}
__device__ __forceinline__ uint32_t pack2h(float a, float b) {
    __half2 hp = __floats2half2_rn(a, b);
    return *(uint32_t*)&hp;
}

__device__ __forceinline__ void mma_f16(float* c, const uint32_t* a, const uint32_t* b) {
    asm volatile(
        "mma.sync.aligned.m16n8k16.row.col.f32.f16.f16.f32 "
        "{%0,%1,%2,%3}, {%4,%5,%6,%7}, {%8,%9}, {%0,%1,%2,%3};"
        : "+f"(c[0]), "+f"(c[1]), "+f"(c[2]), "+f"(c[3])
        : "r"(a[0]), "r"(a[1]), "r"(a[2]), "r"(a[3]), "r"(b[0]), "r"(b[1]));
}

// 2-pass hi/lo GEMM core: acc += (Whi + Wlo)(128xK=128) x Xsingle(K x 128)
// Warp tile 64x32: mf 0..3 (16 rows each), nf 0..3 (8 cols each).
__device__ __forceinline__ void gemm2(const char* smem, float (*acc)[4][4],
                                      int WM, int WN, int g, int t) {
    for (int cb = 0; cb < 2; cb++) {
        const uint32_t* A32 = (const uint32_t*)(smem + (cb ? W_L : W_H));
        const uint32_t* B32 = (const uint32_t*)(smem + X_S);
#pragma unroll
        for (int ks = 0; ks < 8; ks++) {
            int ko = ks * 8 + t;
            uint32_t a[4][4], bb[4][2];
#pragma unroll
            for (int mf = 0; mf < 4; mf++) {
                int r = (WM + mf * 16 + g) * PW32 + ko;
                a[mf][0] = A32[r];
                a[mf][1] = A32[r + 8 * PW32];
                a[mf][2] = A32[r + 4];
                a[mf][3] = A32[r + 8 * PW32 + 4];
            }
#pragma unroll
            for (int nf = 0; nf < 4; nf++) {
                int r = (WN + nf * 8 + g) * PW32 + ko;
                bb[nf][0] = B32[r];
                bb[nf][1] = B32[r + 4];
            }
#pragma unroll
            for (int mf = 0; mf < 4; mf++)
#pragma unroll
                for (int nf = 0; nf < 4; nf++)
                    mma_f16(acc[mf][nf], a[mf], bb[nf]);
        }
    }
}

// ---- K0: zero accumulators (graph replays!) ----
__global__ void k_zero() {
    int i = blockIdx.x * 256 + threadIdx.x;
    if (i < Bn*Hn*Dn*Dn) g_ctx[i] = 0.f;
    if (i < Bn*Hn*Dn)    g_Z[i]   = 0.f;
    if (i < Bn)          { g_bsum[i] = 0.f; g_bsq[i] = 0.f; }
}

// ======== K1: HMMA QKV GEMM + fused q-softmax + exp(k) ========
// CTA: 128 positions x 3 m-tiles of 128 out channels, K=128. 2 CTAs/SM.
__global__ __launch_bounds__(256, 2) void k_qkv_mma(const float* __restrict__ x,
                                                    const float* __restrict__ Wqkv) {
    extern __shared__ __align__(16) char smem[];
    int tid = threadIdx.x, wid = tid >> 5, lid = tid & 31;
    int g = lid >> 2, t = lid & 3;
    int WM = (wid & 1) * 64, WN = (wid >> 1) * 32;
    int p0 = blockIdx.x * 128;
    int b = p0 >> 14, l0 = p0 & (Ln - 1);
    uint32_t* XS = (uint32_t*)(smem + X_S);
    uint32_t* WHp = (uint32_t*)(smem + W_H);
    uint32_t* WLp = (uint32_t*)(smem + W_L);

    // ---- load X tile: 128 pos x 128 ch, single fp16 ----
    const float4* x4 = (const float4*)(x + (size_t)p0 * Cn);
#pragma unroll
    for (int it = 0; it < 16; it++) {
        int f = it * 256 + tid, row = f >> 5, u = f & 31;
        float4 v = x4[f];
        int wb = row * PW32 + u * 2;
        XS[wb]     = pack2h(v.x, v.y);
        XS[wb + 1] = pack2h(v.z, v.w);
    }

    for (int mt = 0; mt < 3; mt++) {
        // ---- load + split W m-tile: 128 x 128, fp16 hi/lo ----
        const float4* w4 = (const float4*)(Wqkv + (size_t)mt * Cn * Cn);
#pragma unroll
        for (int it = 0; it < 16; it++) {
            int f = it * 256 + tid, row = f >> 5, u = f & 31;
            float4 v = w4[f];
            uint32_t h0, l0w, h1, l1w;
            split2h(v.x, v.y, h0, l0w);
            split2h(v.z, v.w, h1, l1w);
            int wb = row * PW32 + u * 2;
            WHp[wb] = h0; WHp[wb + 1] = h1;
            WLp[wb] = l0w; WLp[wb + 1] = l1w;
        }
        __syncthreads();

        float acc[4][4][4];
#pragma unroll
        for (int mf = 0; mf < 4; mf++)
#pragma unroll
            for (int nf = 0; nf < 4; nf++)
#pragma unroll
                for (int q = 0; q < 4; q++) acc[mf][nf][q] = 0.f;

        gemm2(smem, acc, WM, WN, g, t);
        __syncthreads();

        if (mt == 0) {
            // q: stage full 128x128 transposed in W region, softmax over head-dim
            float* qs = (float*)(smem + W_H);
#pragma unroll
            for (int mf = 0; mf < 4; mf++)
#pragma unroll
                for (int nf = 0; nf < 4; nf++) {
                    int m = WM + mf * 16 + g;
                    int nl = WN + nf * 8 + 2 * t;
                    qs[nl * 129 + m]           = acc[mf][nf][0];
                    qs[(nl + 1) * 129 + m]     = acc[mf][nf][1];
                    qs[nl * 129 + m + 8]       = acc[mf][nf][2];
                    qs[(nl + 1) * 129 + m + 8] = acc[mf][nf][3];
                }
            __syncthreads();
            int pos = tid >> 1, hb = (tid & 1) * 64;
            size_t gq = ((size_t)(b * Ln + l0 + pos)) * Cn + hb;
#pragma unroll
            for (int hh = 0; hh < 2; hh++) {
                float vv[32]; float mx = -1e30f;
#pragma unroll
                for (int d = 0; d < 32; d++) {
                    vv[d] = qs[pos * 129 + hb + hh * 32 + d];
                    mx = fmaxf(mx, vv[d]);
                }
                float s = 0.f;
#pragma unroll
                for (int d = 0; d < 32; d++) { vv[d] = __expf(vv[d] - mx); s += vv[d]; }
                float inv = 0.17677669529663689f / s;   // d^-0.5 / s
                uint32_t ph[16];
#pragma unroll
                for (int d2 = 0; d2 < 16; d2++)
                    ph[d2] = pack2h(vv[2 * d2] * inv, vv[2 * d2 + 1] * inv);
                uint4* dh = (uint4*)(g_qb + gq + hh * 32);
#pragma unroll
                for (int w = 0; w < 4; w++)
                    dh[w] = make_uint4(ph[4*w], ph[4*w+1], ph[4*w+2], ph[4*w+3]);
            }
            __syncthreads();
        } else {
            // k -> exp(k); v -> raw; channel-major [b, ch, l], fp16
            __half* gk = g_kv + ((size_t)(b * 256 + (mt - 1) * 128)) * Ln + l0;
#pragma unroll
            for (int mf = 0; mf < 4; mf++)
#pragma unroll
                for (int nf = 0; nf < 4; nf++) {
                    int m = WM + mf * 16 + g;
                    int n0 = WN + nf * 8 + 2 * t;
                    float c0 = acc[mf][nf][0], c1 = acc[mf][nf][1];
                    float c2 = acc[mf][nf][2], c3 = acc[mf][nf][3];
                    if (mt == 1) {
                        c0 = __expf(c0); c1 = __expf(c1);
                        c2 = __expf(c2); c3 = __expf(c3);
                    }
                    *(uint32_t*)(gk + (size_t)m * Ln + n0)       = pack2h(c0, c1);
                    *(uint32_t*)(gk + (size_t)(m + 8) * Ln + n0) = pack2h(c2, c3);
                }
            __syncthreads();
        }
    }
}

// ---- K3: context[bh,c,d] += sum_j ek[c,j] v[d,j]; Z[bh,c] += sum_j ek[c,j] ----
// fp16 inputs, half2 smem tiles, 4x4 register tiling.
__global__ __launch_bounds__(256) void k_ctx() {
    __shared__ __half2 ks[32][17];
    __shared__ __half2 vs[32][17];
    int t = threadIdx.x;
    int bh = blockIdx.x;
    int b = bh >> 2, h = bh & 3;
    const __half* kbase = g_kv + (size_t)(b * 256 + h * Dn) * Ln;
    const __half* vbase = g_kv + (size_t)(b * 256 + 128 + h * Dn) * Ln;
    int j0base = blockIdx.y * 1024;
    int g = t >> 6;             // j subgroup 0..3 (8 j = 4 half2 each)
    int w = t & 63;
    int c4 = (w >> 3) * 4;
    int d4 = (w & 7) * 4;
    float acc[4][4];
#pragma unroll
    for (int i = 0; i < 4; i++)
#pragma unroll
        for (int k = 0; k < 4; k++) acc[i][k] = 0.f;
    float zl = 0.f;

    for (int jb = 0; jb < 32; jb++) {
        int j0 = j0base + jb * 32;
#pragma unroll
        for (int it = 0; it < 2; it++) {
            int idx = it * 256 + t;          // 0..511
            int c = idx >> 4, u = idx & 15;  // 32 rows x 16 half2 words
            ks[c][u] = ((const __half2*)(kbase + (size_t)c * Ln + j0))[u];
            vs[c][u] = ((const __half2*)(vbase + (size_t)c * Ln + j0))[u];
        }
        __syncthreads();
#pragma unroll
        for (int jj = 0; jj < 4; jj++) {
            int j2 = g * 4 + jj;
            float2 e[4], v[4];
#pragma unroll
            for (int i = 0; i < 4; i++) {
                e[i] = __half22float2(ks[c4 + i][j2]);
                v[i] = __half22float2(vs[d4 + i][j2]);
            }
#pragma unroll
            for (int i = 0; i < 4; i++)
#pragma unroll
                for (int k = 0; k < 4; k++)
                    acc[i][k] += e[i].x * v[k].x + e[i].y * v[k].y;
        }
        if (w < 32) {
#pragma unroll
            for (int jj = 0; jj < 4; jj++) {
                float2 z2 = __half22float2(ks[w][g * 4 + jj]);
                zl += z2.x + z2.y;
            }
        }
        __syncthreads();
    }
#pragma unroll
    for (int i = 0; i < 4; i++)
#pragma unroll
        for (int k = 0; k < 4; k++)
            atomicAdd(&g_ctx[bh * 1024 + (c4 + i) * 32 + d4 + k], acc[i][k]);
    if (w < 32) atomicAdd(&g_Z[bh * 32 + w], zl);
}

// ---- K4: A_b = Wout @ blockdiag(ctx/Z), fp16 hi/lo. One output per thread. ----
__global__ __launch_bounds__(256) void k_A(const float* __restrict__ Wout) {
    __shared__ float rZ[128];
    int t = threadIdx.x;
    int b = blockIdx.y;
    if (t < 128) rZ[t] = 1.f / g_Z[b * 128 + t];
    __syncthreads();
    int idx = blockIdx.x * 256 + t;        // 0..16383
    int o = idx >> 7, jcol = idx & 127;
    int h = jcol >> 5, d = jcol & 31;
    const float* wrow = Wout + o * Cn + h * Dn;         // warp-uniform (broadcast)
    const float* cb = g_ctx + b * 4096 + h * 1024 + d;  // lanes d coalesce
    const float* rz = rZ + h * Dn;
    float s = 0.f;
#pragma unroll
    for (int c = 0; c < 32; c++) s += wrow[c] * rz[c] * cb[c * 32];
    __half hb = __float2half(s);
    g_Ah[b * Cn * Cn + idx] = hb;
    g_Al[b * Cn * Cn + idx] = __float2half(s - __half2float(hb));
}

// ======== K5: HMMA out GEMM: o = A_b @ q + bias; accumulate sum/sumsq ========
__global__ __launch_bounds__(256, 2) void k_out_mma(const float* __restrict__ bout) {
    extern __shared__ __align__(16) char smem[];
    int tid = threadIdx.x, wid = tid >> 5, lid = tid & 31;
    int g = lid >> 2, t = lid & 3;
    int WM = (wid & 1) * 64, WN = (wid >> 1) * 32;
    int p0 = blockIdx.x * 128;
    int b = p0 >> 14, l0 = p0 & (Ln - 1);
    uint32_t* XS = (uint32_t*)(smem + X_S);
    uint32_t* WHp = (uint32_t*)(smem + W_H);
    uint32_t* WLp = (uint32_t*)(smem + W_L);

    // Q tile (single fp16, [l][c] K-major rows of 256B): 128 rows
    const uint4* q4 = (const uint4*)(g_qb + (size_t)p0 * Cn);
#pragma unroll
    for (int it = 0; it < 8; it++) {
        int f = it * 256 + tid, row = f >> 4, u = f & 15;
        *(uint4*)(XS + row * PW32 + u * 4) = q4[f];
    }
    // A tiles (fp16 hi/lo)
    const uint4* ah4 = (const uint4*)(g_Ah + (size_t)b * Cn * Cn);
    const uint4* al4 = (const uint4*)(g_Al + (size_t)b * Cn * Cn);
#pragma unroll
    for (int it = 0; it < 8; it++) {
        int f = it * 256 + tid, row = f >> 4, u = f & 15;
        *(uint4*)(WHp + row * PW32 + u * 4) = ah4[f];
        *(uint4*)(WLp + row * PW32 + u * 4) = al4[f];
    }
    __syncthreads();

    float acc[4][4][4];
#pragma unroll
    for (int mf = 0; mf < 4; mf++)
#pragma unroll
        for (int nf = 0; nf < 4; nf++)
#pragma unroll
            for (int q = 0; q < 4; q++) acc[mf][nf][q] = 0.f;

    gemm2(smem, acc, WM, WN, g, t);
    __syncthreads();

    float lsum = 0.f, lsq = 0.f;
    __half* go = g_o + ((size_t)b * Cn) * Ln + l0;
#pragma unroll
    for (int mf = 0; mf < 4; mf++) {
        int m = WM + mf * 16 + g;
        float b0v = bout[m], b1v = bout[m + 8];
#pragma unroll
        for (int nf = 0; nf < 4; nf++) {
            int n0 = WN + nf * 8 + 2 * t;
            float c0 = acc[mf][nf][0] + b0v, c1 = acc[mf][nf][1] + b0v;
            float c2 = acc[mf][nf][2] + b1v, c3 = acc[mf][nf][3] + b1v;
            lsum += c0 + c1 + c2 + c3;
            lsq  += c0 * c0 + c1 * c1 + c2 * c2 + c3 * c3;
            *(uint32_t*)(go + (size_t)m * Ln + n0)       = pack2h(c0, c1);
            *(uint32_t*)(go + (size_t)(m + 8) * Ln + n0) = pack2h(c2, c3);
        }
    }
    float* red = (float*)(smem + W_H);
    red[tid] = lsum; __syncthreads();
    for (int s = 128; s > 0; s >>= 1) { if (tid < s) red[tid] += red[tid + s]; __syncthreads(); }
    if (tid == 0) atomicAdd(&g_bsum[b], red[0]);
    __syncthreads();
    red[tid] = lsq; __syncthreads();
    for (int s = 128; s > 0; s >>= 1) { if (tid < s) red[tid] += red[tid + s]; __syncthreads(); }
    if (tid == 0) atomicAdd(&g_bsq[b], red[0]);
}

// ---- K6: GroupNorm(1,C) + transpose to [b, l, c]; fp16 g_o in, fp32 out ----
// block (32,8): 32 channels x 64 positions per block.
__global__ void k_norm(const float* __restrict__ gnw, const float* __restrict__ gnb,
                       float* __restrict__ out) {
    __shared__ float tile[32][65];
    int b  = blockIdx.z;
    int c0 = blockIdx.y * 32;
    int l0 = blockIdx.x * 64;
    const float n = 2097152.0f;           // C*L
    float mean = g_bsum[b] / n;
    float var  = g_bsq[b] / n - mean * mean;
    float rstd = rsqrtf(var + 1e-5f);
    int tx = threadIdx.x, ty = threadIdx.y;
#pragma unroll
    for (int r = 0; r < 4; r++) {
        int cy = ty * 4 + r;
        __half2 h2 = ((const __half2*)(g_o + (size_t)(b * Cn + c0 + cy) * Ln + l0))[tx];
        float2 f = __half22float2(h2);
        tile[cy][2 * tx]     = f.x;
        tile[cy][2 * tx + 1] = f.y;
    }
    __syncthreads();
    int cch = c0 + tx;
    float w = gnw[cch], bb = gnb[cch];
#pragma unroll
    for (int r = 0; r < 8; r++) {
        int ly = ty * 8 + r;
        float v = (tile[tx][ly] - mean) * rstd * w + bb;
        out[(size_t)(b * Ln + l0 + ly) * Cn + cch] = v;
    }
}

extern "C" void kernel_launch(void* const* d_in, const int* in_sizes, int n_in,
                              void* d_out, int out_size) {
    const float* x    = (const float*)d_in[0];
    const float* Wqkv = (const float*)d_in[1];
    const float* Wout = (const float*)d_in[2];
    const float* bout = (const float*)d_in[3];
    const float* gnw  = (const float*)d_in[4];
    const float* gnb  = (const float*)d_in[5];
    float* out = (float*)d_out;

    cudaFuncSetAttribute(k_qkv_mma, cudaFuncAttributeMaxDynamicSharedMemorySize, SM_TOT);
    cudaFuncSetAttribute(k_out_mma, cudaFuncAttributeMaxDynamicSharedMemorySize, SM_TOT);

    k_zero<<<128, 256>>>();
    k_qkv_mma<<<(Bn * Ln) / 128, 256, SM_TOT>>>(x, Wqkv);
    k_ctx<<<dim3(Bn * Hn, 16), 256>>>();
    k_A<<<dim3(64, Bn), 256>>>(Wout);
    k_out_mma<<<(Bn * Ln) / 128, 256, SM_TOT>>>(bout);
    k_norm<<<dim3(Ln / 64, Cn / 32, Bn), dim3(32, 8)>>>(gnw, gnb, out);
}